// round 1
// baseline (speedup 1.0000x reference)
#include <cuda_runtime.h>
#include <math.h>

#define BB 16
#define KK 256
#define ZZ 128
#define HH 128

// Scratch (allocation-free rule: __device__ globals)
__device__ float g_m1[BB*KK*ZZ];   // m1z
__device__ float g_m2[BB*KK*ZZ];   // m2z
__device__ float g_m [BB*KK*ZZ];   // relu(m1z + masked max)

typedef unsigned long long u64;

__device__ __forceinline__ u64 pack2(float lo, float hi){
    u64 r; asm("mov.b64 %0,{%1,%2};" : "=l"(r) : "f"(lo), "f"(hi)); return r;
}
__device__ __forceinline__ void unpack2(u64 v, float &lo, float &hi){
    asm("mov.b64 {%0,%1},%2;" : "=f"(lo), "=f"(hi) : "l"(v));
}
__device__ __forceinline__ void fma2(u64 &d, u64 a, u64 b){
    asm("fma.rn.f32x2 %0,%1,%2,%0;" : "+l"(d) : "l"(a), "l"(b));
}

// ---------------------------------------------------------------------------
// K1: m1z = z @ W1^T + b1 ; m2z = z @ W2^T + b2
// X: [4096, 128]. CTA: 32 rows x all 128 cols x both matrices. 256 threads.
// Micro-tile: 2 rows x 8 cols x 2 matrices, packed f32x2 accumulators.
// ---------------------------------------------------------------------------
__global__ __launch_bounds__(256) void k1_gemm(
    const float* __restrict__ z,
    const float* __restrict__ W1, const float* __restrict__ b1,
    const float* __restrict__ W2, const float* __restrict__ b2)
{
    __shared__ __align__(16) float Xs[32][33];
    __shared__ __align__(16) float W1t[32][132];
    __shared__ __align__(16) float W2t[32][132];

    const int tid  = threadIdx.x;
    const int row0 = blockIdx.x * 32;
    const int rg   = tid >> 4;        // 0..15 -> rows 2rg, 2rg+1
    const int ng   = tid & 15;        // 0..15 -> cols ng*8 .. ng*8+7
    const int n0   = ng * 8;

    u64 acc1[2][4], acc2[2][4];
    #pragma unroll
    for (int r = 0; r < 2; r++)
        #pragma unroll
        for (int c = 0; c < 4; c++) { acc1[r][c] = 0ull; acc2[r][c] = 0ull; }

    for (int kc = 0; kc < ZZ; kc += 32) {
        // stage X tile (32 rows x 32 k)
        #pragma unroll
        for (int it = 0; it < 4; it++) {
            int idx = tid + it * 256;
            int r = idx >> 5, kk = idx & 31;
            Xs[r][kk] = z[(row0 + r) * ZZ + kc + kk];
        }
        // stage W chunks transposed (k-major for LDS.128 over n)
        #pragma unroll
        for (int it = 0; it < 16; it++) {
            int idx = tid + it * 256;
            int n = idx >> 5, kk = idx & 31;
            W1t[kk][n] = W1[n * ZZ + kc + kk];
            W2t[kk][n] = W2[n * ZZ + kc + kk];
        }
        __syncthreads();

        #pragma unroll
        for (int kk = 0; kk < 32; kk++) {
            float x0 = Xs[2*rg    ][kk];
            float x1 = Xs[2*rg + 1][kk];
            u64 xp0 = pack2(x0, x0);
            u64 xp1 = pack2(x1, x1);
            float4 wa = *(const float4*)&W1t[kk][n0];
            float4 wb = *(const float4*)&W1t[kk][n0 + 4];
            float4 wc = *(const float4*)&W2t[kk][n0];
            float4 wd = *(const float4*)&W2t[kk][n0 + 4];
            u64 w1p0 = pack2(wa.x, wa.y), w1p1 = pack2(wa.z, wa.w);
            u64 w1p2 = pack2(wb.x, wb.y), w1p3 = pack2(wb.z, wb.w);
            u64 w2p0 = pack2(wc.x, wc.y), w2p1 = pack2(wc.z, wc.w);
            u64 w2p2 = pack2(wd.x, wd.y), w2p3 = pack2(wd.z, wd.w);
            fma2(acc1[0][0], w1p0, xp0); fma2(acc1[0][1], w1p1, xp0);
            fma2(acc1[0][2], w1p2, xp0); fma2(acc1[0][3], w1p3, xp0);
            fma2(acc1[1][0], w1p0, xp1); fma2(acc1[1][1], w1p1, xp1);
            fma2(acc1[1][2], w1p2, xp1); fma2(acc1[1][3], w1p3, xp1);
            fma2(acc2[0][0], w2p0, xp0); fma2(acc2[0][1], w2p1, xp0);
            fma2(acc2[0][2], w2p2, xp0); fma2(acc2[0][3], w2p3, xp0);
            fma2(acc2[1][0], w2p0, xp1); fma2(acc2[1][1], w2p1, xp1);
            fma2(acc2[1][2], w2p2, xp1); fma2(acc2[1][3], w2p3, xp1);
        }
        __syncthreads();
    }

    #pragma unroll
    for (int r = 0; r < 2; r++) {
        int row = row0 + 2*rg + r;
        float o1[8], o2[8];
        #pragma unroll
        for (int c = 0; c < 4; c++) {
            unpack2(acc1[r][c], o1[2*c], o1[2*c+1]);
            unpack2(acc2[r][c], o2[2*c], o2[2*c+1]);
        }
        #pragma unroll
        for (int c = 0; c < 8; c++) { o1[c] += b1[n0+c]; o2[c] += b2[n0+c]; }
        *(float4*)&g_m1[row*ZZ + n0    ] = make_float4(o1[0],o1[1],o1[2],o1[3]);
        *(float4*)&g_m1[row*ZZ + n0 + 4] = make_float4(o1[4],o1[5],o1[6],o1[7]);
        *(float4*)&g_m2[row*ZZ + n0    ] = make_float4(o2[0],o2[1],o2[2],o2[3]);
        *(float4*)&g_m2[row*ZZ + n0 + 4] = make_float4(o2[4],o2[5],o2[6],o2[7]);
    }
}

// ---------------------------------------------------------------------------
// K2: m[b,i,:] = relu(m1z[b,i,:] + max_{j: P[b,j,i]!=0} m2z[b,j,:])
// (relu is monotone and every i has >=1 neighbor, so max commutes inside.)
// Grid (K/16, B). 512 threads: warp = one i (mask uniform), lane = z-quad.
// m2z[b] (128KB) is L1-resident; loads coalesced float4.
// ---------------------------------------------------------------------------
__global__ __launch_bounds__(512) void k2_maxmsg(const int* __restrict__ P)
{
    __shared__ int Ps[KK][16];
    const int b  = blockIdx.y;
    const int i0 = blockIdx.x * 16;
    const int tid = threadIdx.x;

    for (int idx = tid; idx < KK * 16; idx += 512) {
        int j = idx >> 4, il = idx & 15;
        Ps[j][il] = P[(b * KK + j) * KK + i0 + il];
    }
    __syncthreads();

    const int w    = tid >> 5;         // warp id = local i
    const int lane = tid & 31;         // z-quad
    const int i    = i0 + w;

    const float* base = g_m2 + (size_t)b * KK * ZZ + lane * 4;
    float4 acc = make_float4(-INFINITY, -INFINITY, -INFINITY, -INFINITY);

    #pragma unroll 4
    for (int j = 0; j < KK; j++) {
        if (Ps[j][w]) {
            float4 v = *(const float4*)(base + j * ZZ);
            acc.x = fmaxf(acc.x, v.x);
            acc.y = fmaxf(acc.y, v.y);
            acc.z = fmaxf(acc.z, v.z);
            acc.w = fmaxf(acc.w, v.w);
        }
    }

    const size_t off = ((size_t)b * KK + i) * ZZ + lane * 4;
    float4 m1 = *(const float4*)(g_m1 + off);
    float4 m;
    m.x = fmaxf(m1.x + acc.x, 0.f);
    m.y = fmaxf(m1.y + acc.y, 0.f);
    m.z = fmaxf(m1.z + acc.z, 0.f);
    m.w = fmaxf(m1.w + acc.w, 0.f);
    *(float4*)(g_m + off) = m;
}

// ---------------------------------------------------------------------------
// K3: out = relu([z | m] @ Wu^T + bu).  Rows 4096, Kdim 256, N 128.
// CTA: 32 rows x 64 n. 128 threads, micro 2 rows x 8 n, f32x2 accumulators.
// ---------------------------------------------------------------------------
__global__ __launch_bounds__(128) void k3_out(
    const float* __restrict__ z,
    const float* __restrict__ Wu, const float* __restrict__ bu,
    float* __restrict__ out)
{
    __shared__ __align__(16) float Xs[32][33];
    __shared__ __align__(16) float Ws[32][68];

    const int tid = threadIdx.x;
    const int R0  = blockIdx.x * 32;
    const int N0  = blockIdx.y * 64;
    const int ng  = tid & 7;           // 0..7 -> n0 = ng*8
    const int rg  = tid >> 3;          // 0..15 -> rows 2rg, 2rg+1
    const int n0  = ng * 8;

    u64 acc[2][4];
    #pragma unroll
    for (int r = 0; r < 2; r++)
        #pragma unroll
        for (int c = 0; c < 4; c++) acc[r][c] = 0ull;

    for (int kc = 0; kc < 2 * ZZ; kc += 32) {
        #pragma unroll
        for (int it = 0; it < 8; it++) {
            int idx = tid + it * 128;
            int r = idx >> 5, kk = idx & 31;
            int kg = kc + kk;
            float v = (kg < ZZ) ? z[(R0 + r) * ZZ + kg]
                                : g_m[(R0 + r) * ZZ + (kg - ZZ)];
            Xs[r][kk] = v;
        }
        #pragma unroll
        for (int it = 0; it < 16; it++) {
            int idx = tid + it * 128;
            int n = idx >> 5, kk = idx & 31;
            Ws[kk][n] = Wu[(N0 + n) * (2 * ZZ) + kc + kk];
        }
        __syncthreads();

        #pragma unroll
        for (int kk = 0; kk < 32; kk++) {
            float x0 = Xs[2*rg    ][kk];
            float x1 = Xs[2*rg + 1][kk];
            u64 xp0 = pack2(x0, x0);
            u64 xp1 = pack2(x1, x1);
            float4 wa = *(const float4*)&Ws[kk][n0];
            float4 wb = *(const float4*)&Ws[kk][n0 + 4];
            u64 wp0 = pack2(wa.x, wa.y), wp1 = pack2(wa.z, wa.w);
            u64 wp2 = pack2(wb.x, wb.y), wp3 = pack2(wb.z, wb.w);
            fma2(acc[0][0], wp0, xp0); fma2(acc[0][1], wp1, xp0);
            fma2(acc[0][2], wp2, xp0); fma2(acc[0][3], wp3, xp0);
            fma2(acc[1][0], wp0, xp1); fma2(acc[1][1], wp1, xp1);
            fma2(acc[1][2], wp2, xp1); fma2(acc[1][3], wp3, xp1);
        }
        __syncthreads();
    }

    #pragma unroll
    for (int r = 0; r < 2; r++) {
        int row = R0 + 2*rg + r;
        float o[8];
        #pragma unroll
        for (int c = 0; c < 4; c++) unpack2(acc[r][c], o[2*c], o[2*c+1]);
        #pragma unroll
        for (int c = 0; c < 8; c++) o[c] = fmaxf(o[c] + bu[N0 + n0 + c], 0.f);
        *(float4*)&out[row * HH + N0 + n0    ] = make_float4(o[0],o[1],o[2],o[3]);
        *(float4*)&out[row * HH + N0 + n0 + 4] = make_float4(o[4],o[5],o[6],o[7]);
    }
}

// ---------------------------------------------------------------------------
extern "C" void kernel_launch(void* const* d_in, const int* in_sizes, int n_in,
                              void* d_out, int out_size)
{
    const float* z  = (const float*)d_in[0];
    const int*   P  = (const int*)  d_in[1];
    const float* W1 = (const float*)d_in[2];
    const float* b1 = (const float*)d_in[3];
    const float* W2 = (const float*)d_in[4];
    const float* b2 = (const float*)d_in[5];
    const float* Wu = (const float*)d_in[6];
    const float* bu = (const float*)d_in[7];
    float* out = (float*)d_out;

    k1_gemm<<<BB * KK / 32, 256>>>(z, W1, b1, W2, b2);
    k2_maxmsg<<<dim3(KK / 16, BB), 512>>>(P);
    k3_out<<<dim3(BB * KK / 32, HH / 64), 128>>>(z, Wu, bu, out);
}

// round 2
// speedup vs baseline: 1.2031x; 1.2031x over previous
#include <cuda_runtime.h>
#include <math.h>

#define BB 16
#define KK 256
#define ZZ 128
#define HH 128

// Scratch (allocation-free rule: __device__ globals)
__device__ float g_m1[BB*KK*ZZ];   // m1z
__device__ float g_m2[BB*KK*ZZ];   // m2z
__device__ float g_m [BB*KK*ZZ];   // relu(m1z + masked max)

typedef unsigned long long u64;

__device__ __forceinline__ void unpack2(u64 v, float &lo, float &hi){
    asm("mov.b64 {%0,%1},%2;" : "=f"(lo), "=f"(hi) : "l"(v));
}
__device__ __forceinline__ void fma2(u64 &d, u64 a, u64 b){
    asm("fma.rn.f32x2 %0,%1,%2,%0;" : "+l"(d) : "l"(a), "l"(b));
}

// ---------------------------------------------------------------------------
// K1: m{1,2}z = z @ W{1,2}^T + b{1,2}.   X: [4096, 128].
// grid (128 rowtiles, 2 matrices), 128 threads.
// CTA: 32 rows x 128 cols of ONE matrix. Micro-tile 4 rows x 8 cols,
// packed f32x2 accumulators, float4 smem loads for both operands.
// Thread cols are strided 16 so W LDS.128 addresses cover all quad-banks.
// ---------------------------------------------------------------------------
__global__ __launch_bounds__(128, 4) void k1_gemm(
    const float* __restrict__ z,
    const float* __restrict__ W1, const float* __restrict__ b1,
    const float* __restrict__ W2, const float* __restrict__ b2)
{
    __shared__ __align__(16) float Xs[32][68];    // 8.7 KB
    __shared__ __align__(16) float Ws[128][76];   // 38.9 KB

    const int tid  = threadIdx.x;
    const int row0 = blockIdx.x * 32;
    const int mat  = blockIdx.y;
    const float* __restrict__ W = mat ? W2 : W1;
    const float* __restrict__ b = mat ? b2 : b1;
    float* __restrict__ dst     = mat ? g_m2 : g_m1;

    const int rg = tid >> 4;     // 0..7  -> rows 4rg..4rg+3
    const int ng = tid & 15;     // 0..15 -> cols ng + 16*cc

    u64 acc[4][8];
    #pragma unroll
    for (int r = 0; r < 4; r++)
        #pragma unroll
        for (int c = 0; c < 8; c++) acc[r][c] = 0ull;

    for (int kc = 0; kc < ZZ; kc += 64) {
        // stage X: 32 rows x 64 k  (512 float4 / 128 thr = 4 each)
        #pragma unroll
        for (int it = 0; it < 4; it++) {
            int f = tid + it * 128;
            int r = f >> 4, kq = f & 15;
            *(float4*)&Xs[r][4*kq] =
                *(const float4*)&z[(row0 + r) * ZZ + kc + 4*kq];
        }
        // stage W: 128 n x 64 k (2048 float4 / 128 thr = 16 each)
        #pragma unroll
        for (int it = 0; it < 16; it++) {
            int f = tid + it * 128;
            int n = f >> 4, kq = f & 15;
            *(float4*)&Ws[n][4*kq] =
                *(const float4*)&W[n * ZZ + kc + 4*kq];
        }
        __syncthreads();

        #pragma unroll
        for (int kq = 0; kq < 16; kq++) {
            ulonglong2 xq[4];
            #pragma unroll
            for (int rr = 0; rr < 4; rr++)
                xq[rr] = *(const ulonglong2*)&Xs[4*rg + rr][4*kq];
            #pragma unroll
            for (int cc = 0; cc < 8; cc++) {
                ulonglong2 wq = *(const ulonglong2*)&Ws[ng + 16*cc][4*kq];
                #pragma unroll
                for (int rr = 0; rr < 4; rr++) {
                    fma2(acc[rr][cc], xq[rr].x, wq.x);
                    fma2(acc[rr][cc], xq[rr].y, wq.y);
                }
            }
        }
        __syncthreads();
    }

    #pragma unroll
    for (int cc = 0; cc < 8; cc++) {
        float bias = __ldg(&b[ng + 16*cc]);
        #pragma unroll
        for (int rr = 0; rr < 4; rr++) {
            float lo, hi; unpack2(acc[rr][cc], lo, hi);
            dst[(row0 + 4*rg + rr) * ZZ + ng + 16*cc] = lo + hi + bias;
        }
    }
}

// ---------------------------------------------------------------------------
// K2: m[b,i,:] = relu(m1z[b,i,:] + max_{j: P[b,j,i]!=0} m2z[b,j,:])
// (relu monotone + every i has a self-loop neighbor => max commutes inside.)
// Warp = one i. Ballot-compacted neighbor list -> branch-free MLP-4 loop.
// ---------------------------------------------------------------------------
__global__ __launch_bounds__(512) void k2_maxmsg(const int* __restrict__ P)
{
    __shared__ int PsT[16][257];                     // PsT[il][j], 16.4 KB
    __shared__ unsigned char lists[16][256];         // 4 KB
    const int b   = blockIdx.y;
    const int i0  = blockIdx.x * 16;
    const int tid = threadIdx.x;

    // stage transposed mask: PsT[il][j] = P[b][j][i0+il]
    for (int idx = tid; idx < KK * 16; idx += 512) {
        int j = idx >> 4, il = idx & 15;
        PsT[il][j] = P[(b * KK + j) * KK + i0 + il];
    }
    __syncthreads();

    const int w    = tid >> 5;     // warp id = local i
    const int lane = tid & 31;

    // compact neighbor list for i = i0 + w
    int cnt = 0;
    #pragma unroll
    for (int jb = 0; jb < KK; jb += 32) {
        int pj = PsT[w][jb + lane];
        unsigned bal = __ballot_sync(0xffffffffu, pj != 0);
        if (pj) {
            int pos = cnt + __popc(bal & ((1u << lane) - 1u));
            lists[w][pos] = (unsigned char)(jb + lane);
        }
        cnt += __popc(bal);
    }
    __syncwarp();

    const float* base = g_m2 + (size_t)b * KK * ZZ + lane * 4;
    float4 acc = make_float4(-INFINITY, -INFINITY, -INFINITY, -INFINITY);

    int e = 0;
    for (; e + 4 <= cnt; e += 4) {
        uchar4 jj = *(const uchar4*)&lists[w][e];
        float4 v0 = *(const float4*)(base + (int)jj.x * ZZ);
        float4 v1 = *(const float4*)(base + (int)jj.y * ZZ);
        float4 v2 = *(const float4*)(base + (int)jj.z * ZZ);
        float4 v3 = *(const float4*)(base + (int)jj.w * ZZ);
        acc.x = fmaxf(fmaxf(fmaxf(acc.x, v0.x), fmaxf(v1.x, v2.x)), v3.x);
        acc.y = fmaxf(fmaxf(fmaxf(acc.y, v0.y), fmaxf(v1.y, v2.y)), v3.y);
        acc.z = fmaxf(fmaxf(fmaxf(acc.z, v0.z), fmaxf(v1.z, v2.z)), v3.z);
        acc.w = fmaxf(fmaxf(fmaxf(acc.w, v0.w), fmaxf(v1.w, v2.w)), v3.w);
    }
    for (; e < cnt; e++) {
        int j = lists[w][e];
        float4 v = *(const float4*)(base + j * ZZ);
        acc.x = fmaxf(acc.x, v.x);
        acc.y = fmaxf(acc.y, v.y);
        acc.z = fmaxf(acc.z, v.z);
        acc.w = fmaxf(acc.w, v.w);
    }

    const size_t off = ((size_t)b * KK + i0 + w) * ZZ + lane * 4;
    float4 m1 = *(const float4*)(g_m1 + off);
    float4 m;
    m.x = fmaxf(m1.x + acc.x, 0.f);
    m.y = fmaxf(m1.y + acc.y, 0.f);
    m.z = fmaxf(m1.z + acc.z, 0.f);
    m.w = fmaxf(m1.w + acc.w, 0.f);
    *(float4*)(g_m + off) = m;
}

// ---------------------------------------------------------------------------
// K3: out = relu([z | m] @ Wu^T + bu).  Rows 4096, Kdim 256, N 128.
// grid (128 rowtiles, 2 n-halves), 128 threads.
// CTA: 32 rows x 64 cols. Micro-tile 4 rows x 4 cols (cols strided 16).
// ---------------------------------------------------------------------------
__global__ __launch_bounds__(128, 4) void k3_out(
    const float* __restrict__ z,
    const float* __restrict__ Wu, const float* __restrict__ bu,
    float* __restrict__ out)
{
    __shared__ __align__(16) float Xs[32][68];   // 8.7 KB
    __shared__ __align__(16) float Ws[64][76];   // 19.5 KB

    const int tid  = threadIdx.x;
    const int row0 = blockIdx.x * 32;
    const int N0   = blockIdx.y * 64;
    const int rg   = tid >> 4;     // 0..7  -> 4 rows
    const int ng   = tid & 15;     // 0..15 -> cols ng + 16*cc (cc 0..3)

    u64 acc[4][4];
    #pragma unroll
    for (int r = 0; r < 4; r++)
        #pragma unroll
        for (int c = 0; c < 4; c++) acc[r][c] = 0ull;

    for (int kc = 0; kc < 2 * ZZ; kc += 64) {
        const float* __restrict__ src =
            (kc < ZZ) ? (z + (size_t)row0 * ZZ + kc)
                      : (g_m + (size_t)row0 * ZZ + (kc - ZZ));
        // stage X: 32 rows x 64 k
        #pragma unroll
        for (int it = 0; it < 4; it++) {
            int f = tid + it * 128;
            int r = f >> 4, kq = f & 15;
            *(float4*)&Xs[r][4*kq] = *(const float4*)(src + r * ZZ + 4*kq);
        }
        // stage W: 64 n x 64 k (1024 float4 / 128 thr = 8 each)
        #pragma unroll
        for (int it = 0; it < 8; it++) {
            int f = tid + it * 128;
            int n = f >> 4, kq = f & 15;
            *(float4*)&Ws[n][4*kq] =
                *(const float4*)&Wu[(N0 + n) * (2 * ZZ) + kc + 4*kq];
        }
        __syncthreads();

        #pragma unroll
        for (int kq = 0; kq < 16; kq++) {
            ulonglong2 xq[4];
            #pragma unroll
            for (int rr = 0; rr < 4; rr++)
                xq[rr] = *(const ulonglong2*)&Xs[4*rg + rr][4*kq];
            #pragma unroll
            for (int cc = 0; cc < 4; cc++) {
                ulonglong2 wq = *(const ulonglong2*)&Ws[ng + 16*cc][4*kq];
                #pragma unroll
                for (int rr = 0; rr < 4; rr++) {
                    fma2(acc[rr][cc], xq[rr].x, wq.x);
                    fma2(acc[rr][cc], xq[rr].y, wq.y);
                }
            }
        }
        __syncthreads();
    }

    #pragma unroll
    for (int cc = 0; cc < 4; cc++) {
        float bias = __ldg(&bu[N0 + ng + 16*cc]);
        #pragma unroll
        for (int rr = 0; rr < 4; rr++) {
            float lo, hi; unpack2(acc[rr][cc], lo, hi);
            out[(row0 + 4*rg + rr) * HH + N0 + ng + 16*cc] =
                fmaxf(lo + hi + bias, 0.f);
        }
    }
}

// ---------------------------------------------------------------------------
extern "C" void kernel_launch(void* const* d_in, const int* in_sizes, int n_in,
                              void* d_out, int out_size)
{
    const float* z  = (const float*)d_in[0];
    const int*   P  = (const int*)  d_in[1];
    const float* W1 = (const float*)d_in[2];
    const float* b1 = (const float*)d_in[3];
    const float* W2 = (const float*)d_in[4];
    const float* b2 = (const float*)d_in[5];
    const float* Wu = (const float*)d_in[6];
    const float* bu = (const float*)d_in[7];
    float* out = (float*)d_out;

    k1_gemm<<<dim3(BB * KK / 32, 2), 128>>>(z, W1, b1, W2, b2);
    k2_maxmsg<<<dim3(KK / 16, BB), 512>>>(P);
    k3_out<<<dim3(BB * KK / 32, 2), 128>>>(z, Wu, bu, out);
}

// round 4
// speedup vs baseline: 1.7382x; 1.4448x over previous
#include <cuda_runtime.h>
#include <math.h>

#define BB 16
#define KK 256
#define ZZ 128
#define HH 128
#define M2P 384   // padded row count per batch in g_m2x: 256 m2z rows + 128 pair-max rows

// Scratch (allocation-free rule: __device__ globals)
__device__ float g_m1 [BB*KK*ZZ];    // m1z, [B][256][128]
__device__ float g_m2x[BB*M2P*ZZ];   // rows 0..255: m2z ; rows 256..383: pair-max
__device__ float g_m  [BB*KK*ZZ];    // relu(m1z + masked max)

typedef unsigned long long u64;

__device__ __forceinline__ void unpack2(u64 v, float &lo, float &hi){
    asm("mov.b64 {%0,%1},%2;" : "=f"(lo), "=f"(hi) : "l"(v));
}
__device__ __forceinline__ void fma2(u64 &d, u64 a, u64 b){
    asm("fma.rn.f32x2 %0,%1,%2,%0;" : "+l"(d) : "l"(a), "l"(b));
}

// ---------------------------------------------------------------------------
// K1: m{1,2}z = z @ W{1,2}^T + b{1,2}.   X: [4096, 128].
// grid (128 rowtiles, 4: bit0=colhalf, bit1=matrix), 128 threads.
// CTA: 32 rows x 64 cols. Micro-tile 4 rows x 4 cols (cols strided 16),
// f32x2 accumulators packed over k-pairs. acc = 64 regs -> no spills.
// ---------------------------------------------------------------------------
__global__ __launch_bounds__(128, 4) void k1_gemm(
    const float* __restrict__ z,
    const float* __restrict__ W1, const float* __restrict__ b1,
    const float* __restrict__ W2, const float* __restrict__ b2)
{
    __shared__ __align__(16) float Xs[32][68];   // 8.7 KB
    __shared__ __align__(16) float Ws[64][76];   // 19.5 KB

    const int tid  = threadIdx.x;
    const int row0 = blockIdx.x * 32;
    const int mat  = blockIdx.y >> 1;
    const int N0   = (blockIdx.y & 1) * 64;
    const float* __restrict__ W = mat ? W2 : W1;
    const float* __restrict__ b = mat ? b2 : b1;

    const int rg = tid >> 4;     // 0..7  -> rows 4rg..4rg+3
    const int ng = tid & 15;     // 0..15 -> cols ng + 16*cc

    u64 acc[4][4];
    #pragma unroll
    for (int r = 0; r < 4; r++)
        #pragma unroll
        for (int c = 0; c < 4; c++) acc[r][c] = 0ull;

    for (int kc = 0; kc < ZZ; kc += 64) {
        #pragma unroll
        for (int it = 0; it < 4; it++) {           // X: 32 rows x 64 k
            int f = tid + it * 128;
            int r = f >> 4, kq = f & 15;
            *(float4*)&Xs[r][4*kq] =
                *(const float4*)&z[(row0 + r) * ZZ + kc + 4*kq];
        }
        #pragma unroll
        for (int it = 0; it < 8; it++) {           // W: 64 n x 64 k
            int f = tid + it * 128;
            int n = f >> 4, kq = f & 15;
            *(float4*)&Ws[n][4*kq] =
                *(const float4*)&W[(N0 + n) * ZZ + kc + 4*kq];
        }
        __syncthreads();

        #pragma unroll
        for (int kq = 0; kq < 16; kq++) {
            ulonglong2 xq[4];
            #pragma unroll
            for (int rr = 0; rr < 4; rr++)
                xq[rr] = *(const ulonglong2*)&Xs[4*rg + rr][4*kq];
            #pragma unroll
            for (int cc = 0; cc < 4; cc++) {
                ulonglong2 wq = *(const ulonglong2*)&Ws[ng + 16*cc][4*kq];
                #pragma unroll
                for (int rr = 0; rr < 4; rr++) {
                    fma2(acc[rr][cc], xq[rr].x, wq.x);
                    fma2(acc[rr][cc], xq[rr].y, wq.y);
                }
            }
        }
        __syncthreads();
    }

    #pragma unroll
    for (int cc = 0; cc < 4; cc++) {
        int col = N0 + ng + 16*cc;
        float bias = __ldg(&b[col]);
        #pragma unroll
        for (int rr = 0; rr < 4; rr++) {
            int row = row0 + 4*rg + rr;
            float lo, hi; unpack2(acc[rr][cc], lo, hi);
            float v = lo + hi + bias;
            if (mat == 0) {
                g_m1[row * ZZ + col] = v;
            } else {
                int bb = row >> 8, il = row & 255;
                g_m2x[((size_t)bb * M2P + il) * ZZ + col] = v;
            }
        }
    }
}

// ---------------------------------------------------------------------------
// K2a: pair-max rows: g_m2x[b][256+jp] = max(g_m2x[b][2jp], g_m2x[b][2jp+1])
// 65536 float4 lanes total.
// ---------------------------------------------------------------------------
__global__ __launch_bounds__(256) void k2a_pairmax()
{
    int t  = blockIdx.x * 256 + threadIdx.x;     // 0..65535
    int b  = t >> 12;
    int r  = t & 4095;
    int jp = r >> 5;
    int q  = r & 31;
    const float4* rows = (const float4*)g_m2x;
    float4 a = rows[((size_t)b * M2P + 2*jp    ) * 32 + q];
    float4 c = rows[((size_t)b * M2P + 2*jp + 1) * 32 + q];
    float4 m;
    m.x = fmaxf(a.x, c.x); m.y = fmaxf(a.y, c.y);
    m.z = fmaxf(a.z, c.z); m.w = fmaxf(a.w, c.w);
    ((float4*)g_m2x)[((size_t)b * M2P + 256 + jp) * 32 + q] = m;
}

// ---------------------------------------------------------------------------
// K2: m[b,i,:] = relu(m1z[b,i,:] + max_{j: P[b,j,i]!=0} m2z[b,j,:])
// (relu monotone + self-loop guarantees a neighbor => max commutes inside.)
// Warp = one i. Neighbor j-pairs are collapsed: both present -> 1 read of the
// precomputed pair-max row; else the single present row. <=128 entries.
// ---------------------------------------------------------------------------
__global__ __launch_bounds__(512) void k2_maxmsg(const int* __restrict__ P)
{
    __shared__ int PsT[16][257];                 // PsT[il][j]
    __shared__ unsigned short lists[16][128];
    const int b   = blockIdx.y;
    const int i0  = blockIdx.x * 16;
    const int tid = threadIdx.x;

    for (int idx = tid; idx < KK * 16; idx += 512) {
        int j = idx >> 4, il = idx & 15;
        PsT[il][j] = P[(b * KK + j) * KK + i0 + il];
    }
    __syncthreads();

    const int w    = tid >> 5;     // warp id = local i
    const int lane = tid & 31;

    int cnt = 0;
    #pragma unroll
    for (int jb = 0; jb < 128; jb += 32) {       // jp = pair index
        int jp = jb + lane;
        int f0 = PsT[w][2*jp];
        int f1 = PsT[w][2*jp + 1];
        int present = (f0 | f1) != 0;
        int idx = (f0 && f1) ? (256 + jp) : (f0 ? 2*jp : 2*jp + 1);
        unsigned bal = __ballot_sync(0xffffffffu, present);
        if (present) {
            int pos = cnt + __popc(bal & ((1u << lane) - 1u));
            lists[w][pos] = (unsigned short)idx;
        }
        cnt += __popc(bal);
    }
    __syncwarp();

    const float* base = g_m2x + (size_t)b * M2P * ZZ + lane * 4;
    float4 acc = make_float4(-INFINITY, -INFINITY, -INFINITY, -INFINITY);

    int e = 0;
    for (; e + 4 <= cnt; e += 4) {
        ushort4 jj = *(const ushort4*)&lists[w][e];
        float4 v0 = *(const float4*)(base + (int)jj.x * ZZ);
        float4 v1 = *(const float4*)(base + (int)jj.y * ZZ);
        float4 v2 = *(const float4*)(base + (int)jj.z * ZZ);
        float4 v3 = *(const float4*)(base + (int)jj.w * ZZ);
        acc.x = fmaxf(fmaxf(fmaxf(acc.x, v0.x), fmaxf(v1.x, v2.x)), v3.x);
        acc.y = fmaxf(fmaxf(fmaxf(acc.y, v0.y), fmaxf(v1.y, v2.y)), v3.y);
        acc.z = fmaxf(fmaxf(fmaxf(acc.z, v0.z), fmaxf(v1.z, v2.z)), v3.z);
        acc.w = fmaxf(fmaxf(fmaxf(acc.w, v0.w), fmaxf(v1.w, v2.w)), v3.w);
    }
    for (; e < cnt; e++) {
        int j = lists[w][e];
        float4 v = *(const float4*)(base + j * ZZ);
        acc.x = fmaxf(acc.x, v.x);
        acc.y = fmaxf(acc.y, v.y);
        acc.z = fmaxf(acc.z, v.z);
        acc.w = fmaxf(acc.w, v.w);
    }

    const size_t off = ((size_t)b * KK + i0 + w) * ZZ + lane * 4;
    float4 m1 = *(const float4*)(g_m1 + off);
    float4 m;
    m.x = fmaxf(m1.x + acc.x, 0.f);
    m.y = fmaxf(m1.y + acc.y, 0.f);
    m.z = fmaxf(m1.z + acc.z, 0.f);
    m.w = fmaxf(m1.w + acc.w, 0.f);
    *(float4*)(g_m + off) = m;
}

// ---------------------------------------------------------------------------
// K3: out = relu([z | m] @ Wu^T + bu).  Rows 4096, Kdim 256, N 128.
// grid (256 rowtiles, 2 colhalves), 128 threads.
// CTA: 16 rows x 64 cols. Micro-tile 2 rows x 4 cols.
// ---------------------------------------------------------------------------
__global__ __launch_bounds__(128, 8) void k3_out(
    const float* __restrict__ z,
    const float* __restrict__ Wu, const float* __restrict__ bu,
    float* __restrict__ out)
{
    __shared__ __align__(16) float Xs[16][68];   // 4.4 KB
    __shared__ __align__(16) float Ws[64][76];   // 19.5 KB

    const int tid  = threadIdx.x;
    const int row0 = blockIdx.x * 16;
    const int N0   = blockIdx.y * 64;
    const int rg   = tid >> 4;     // 0..7  -> rows 2rg, 2rg+1
    const int ng   = tid & 15;     // 0..15 -> cols ng + 16*cc

    u64 acc[2][4];
    #pragma unroll
    for (int r = 0; r < 2; r++)
        #pragma unroll
        for (int c = 0; c < 4; c++) acc[r][c] = 0ull;

    for (int kc = 0; kc < 2 * ZZ; kc += 64) {
        const float* __restrict__ src =
            (kc < ZZ) ? (z + (size_t)row0 * ZZ + kc)
                      : (g_m + (size_t)row0 * ZZ + (kc - ZZ));
        #pragma unroll
        for (int it = 0; it < 2; it++) {           // X: 16 rows x 64 k
            int f = tid + it * 128;
            int r = f >> 4, kq = f & 15;
            *(float4*)&Xs[r][4*kq] = *(const float4*)(src + r * ZZ + 4*kq);
        }
        #pragma unroll
        for (int it = 0; it < 8; it++) {           // W: 64 n x 64 k
            int f = tid + it * 128;
            int n = f >> 4, kq = f & 15;
            *(float4*)&Ws[n][4*kq] =
                *(const float4*)&Wu[(N0 + n) * (2 * ZZ) + kc + 4*kq];
        }
        __syncthreads();

        #pragma unroll
        for (int kq = 0; kq < 16; kq++) {
            ulonglong2 xq[2];
            #pragma unroll
            for (int rr = 0; rr < 2; rr++)
                xq[rr] = *(const ulonglong2*)&Xs[2*rg + rr][4*kq];
            #pragma unroll
            for (int cc = 0; cc < 4; cc++) {
                ulonglong2 wq = *(const ulonglong2*)&Ws[ng + 16*cc][4*kq];
                #pragma unroll
                for (int rr = 0; rr < 2; rr++) {
                    fma2(acc[rr][cc], xq[rr].x, wq.x);
                    fma2(acc[rr][cc], xq[rr].y, wq.y);
                }
            }
        }
        __syncthreads();
    }

    #pragma unroll
    for (int cc = 0; cc < 4; cc++) {
        int col = N0 + ng + 16*cc;
        float bias = __ldg(&bu[col]);
        #pragma unroll
        for (int rr = 0; rr < 2; rr++) {
            float lo, hi; unpack2(acc[rr][cc], lo, hi);
            out[(row0 + 2*rg + rr) * HH + col] = fmaxf(lo + hi + bias, 0.f);
        }
    }
}

// ---------------------------------------------------------------------------
extern "C" void kernel_launch(void* const* d_in, const int* in_sizes, int n_in,
                              void* d_out, int out_size)
{
    const float* z  = (const float*)d_in[0];
    const int*   P  = (const int*)  d_in[1];
    const float* W1 = (const float*)d_in[2];
    const float* b1 = (const float*)d_in[3];
    const float* W2 = (const float*)d_in[4];
    const float* b2 = (const float*)d_in[5];
    const float* Wu = (const float*)d_in[6];
    const float* bu = (const float*)d_in[7];
    float* out = (float*)d_out;

    k1_gemm<<<dim3(BB * KK / 32, 4), 128>>>(z, W1, b1, W2, b2);
    k2a_pairmax<<<256, 256>>>();
    k2_maxmsg<<<dim3(KK / 16, BB), 512>>>(P);
    k3_out<<<dim3(BB * KK / 16, 2), 128>>>(z, Wu, bu, out);
}

// round 5
// speedup vs baseline: 1.8271x; 1.0511x over previous
#include <cuda_runtime.h>
#include <math.h>

#define BB 16
#define KK 256
#define ZZ 128
#define HH 128
#define M2P 384   // padded row count per batch in g_m2x: 256 m2z rows + 128 pair-max rows

// Scratch (allocation-free rule: __device__ globals)
__device__ float g_m1 [BB*KK*ZZ];    // m1z, [B][256][128]
__device__ float g_m2x[BB*M2P*ZZ];   // rows 0..255: m2z ; rows 256..383: pair-max
__device__ float g_m  [BB*KK*ZZ];    // relu(m1z + masked max)
__device__ float g_p  [2*BB*KK*HH];  // k3 split-K partials

typedef unsigned long long u64;

__device__ __forceinline__ void unpack2(u64 v, float &lo, float &hi){
    asm("mov.b64 {%0,%1},%2;" : "=f"(lo), "=f"(hi) : "l"(v));
}
__device__ __forceinline__ void fma2(u64 &d, u64 a, u64 b){
    asm("fma.rn.f32x2 %0,%1,%2,%0;" : "+l"(d) : "l"(a), "l"(b));
}

// ---------------------------------------------------------------------------
// K1: m{1,2}z = z @ W{1,2}^T + b{1,2}.   X: [4096, 128].
// grid (128 rowtiles, 4: bit0=colhalf, bit1=matrix), 128 threads.
// CTA: 32 rows x 64 cols. Micro-tile 4 rows x 4 cols (cols strided 16),
// f32x2 accumulators packed over k-pairs.
// ---------------------------------------------------------------------------
__global__ __launch_bounds__(128, 4) void k1_gemm(
    const float* __restrict__ z,
    const float* __restrict__ W1, const float* __restrict__ b1,
    const float* __restrict__ W2, const float* __restrict__ b2)
{
    __shared__ __align__(16) float Xs[32][68];   // 8.7 KB
    __shared__ __align__(16) float Ws[64][76];   // 19.5 KB

    const int tid  = threadIdx.x;
    const int row0 = blockIdx.x * 32;
    const int mat  = blockIdx.y >> 1;
    const int N0   = (blockIdx.y & 1) * 64;
    const float* __restrict__ W = mat ? W2 : W1;
    const float* __restrict__ b = mat ? b2 : b1;

    const int rg = tid >> 4;     // 0..7  -> rows 4rg..4rg+3
    const int ng = tid & 15;     // 0..15 -> cols ng + 16*cc

    u64 acc[4][4];
    #pragma unroll
    for (int r = 0; r < 4; r++)
        #pragma unroll
        for (int c = 0; c < 4; c++) acc[r][c] = 0ull;

    for (int kc = 0; kc < ZZ; kc += 64) {
        #pragma unroll
        for (int it = 0; it < 4; it++) {           // X: 32 rows x 64 k
            int f = tid + it * 128;
            int r = f >> 4, kq = f & 15;
            *(float4*)&Xs[r][4*kq] =
                *(const float4*)&z[(row0 + r) * ZZ + kc + 4*kq];
        }
        #pragma unroll
        for (int it = 0; it < 8; it++) {           // W: 64 n x 64 k
            int f = tid + it * 128;
            int n = f >> 4, kq = f & 15;
            *(float4*)&Ws[n][4*kq] =
                *(const float4*)&W[(N0 + n) * ZZ + kc + 4*kq];
        }
        __syncthreads();

        #pragma unroll
        for (int kq = 0; kq < 16; kq++) {
            ulonglong2 xq[4];
            #pragma unroll
            for (int rr = 0; rr < 4; rr++)
                xq[rr] = *(const ulonglong2*)&Xs[4*rg + rr][4*kq];
            #pragma unroll
            for (int cc = 0; cc < 4; cc++) {
                ulonglong2 wq = *(const ulonglong2*)&Ws[ng + 16*cc][4*kq];
                #pragma unroll
                for (int rr = 0; rr < 4; rr++) {
                    fma2(acc[rr][cc], xq[rr].x, wq.x);
                    fma2(acc[rr][cc], xq[rr].y, wq.y);
                }
            }
        }
        __syncthreads();
    }

    #pragma unroll
    for (int cc = 0; cc < 4; cc++) {
        int col = N0 + ng + 16*cc;
        float bias = __ldg(&b[col]);
        #pragma unroll
        for (int rr = 0; rr < 4; rr++) {
            int row = row0 + 4*rg + rr;
            float lo, hi; unpack2(acc[rr][cc], lo, hi);
            float v = lo + hi + bias;
            if (mat == 0) {
                g_m1[row * ZZ + col] = v;
            } else {
                int bb = row >> 8, il = row & 255;
                g_m2x[((size_t)bb * M2P + il) * ZZ + col] = v;
            }
        }
    }
}

// ---------------------------------------------------------------------------
// K2a: pair-max rows: g_m2x[b][256+jp] = max(g_m2x[b][2jp], g_m2x[b][2jp+1])
// ---------------------------------------------------------------------------
__global__ __launch_bounds__(256) void k2a_pairmax()
{
    int t  = blockIdx.x * 256 + threadIdx.x;     // 0..65535
    int b  = t >> 12;
    int r  = t & 4095;
    int jp = r >> 5;
    int q  = r & 31;
    const float4* rows = (const float4*)g_m2x;
    float4 a = rows[((size_t)b * M2P + 2*jp    ) * 32 + q];
    float4 c = rows[((size_t)b * M2P + 2*jp + 1) * 32 + q];
    float4 m;
    m.x = fmaxf(a.x, c.x); m.y = fmaxf(a.y, c.y);
    m.z = fmaxf(a.z, c.z); m.w = fmaxf(a.w, c.w);
    ((float4*)g_m2x)[((size_t)b * M2P + 256 + jp) * 32 + q] = m;
}

// ---------------------------------------------------------------------------
// K2: m[b,i,:] = relu(m1z[b,i,:] + max_{j: P[b,j,i]!=0} m2z[b,j,:])
// Warp = one i. Pair-collapsed neighbor list, unroll-8 MLP loop.
// ---------------------------------------------------------------------------
__global__ __launch_bounds__(512) void k2_maxmsg(const int* __restrict__ P)
{
    __shared__ int PsT[16][257];                 // PsT[il][j]
    __shared__ unsigned short lists[16][128];
    const int b   = blockIdx.y;
    const int i0  = blockIdx.x * 16;
    const int tid = threadIdx.x;

    for (int idx = tid; idx < KK * 16; idx += 512) {
        int j = idx >> 4, il = idx & 15;
        PsT[il][j] = P[(b * KK + j) * KK + i0 + il];
    }
    __syncthreads();

    const int w    = tid >> 5;     // warp id = local i
    const int lane = tid & 31;

    int cnt = 0;
    #pragma unroll
    for (int jb = 0; jb < 128; jb += 32) {       // jp = pair index
        int jp = jb + lane;
        int f0 = PsT[w][2*jp];
        int f1 = PsT[w][2*jp + 1];
        int present = (f0 | f1) != 0;
        int idx = (f0 && f1) ? (256 + jp) : (f0 ? 2*jp : 2*jp + 1);
        unsigned bal = __ballot_sync(0xffffffffu, present);
        if (present) {
            int pos = cnt + __popc(bal & ((1u << lane) - 1u));
            lists[w][pos] = (unsigned short)idx;
        }
        cnt += __popc(bal);
    }
    __syncwarp();

    const float* base = g_m2x + (size_t)b * M2P * ZZ + lane * 4;
    float4 acc = make_float4(-INFINITY, -INFINITY, -INFINITY, -INFINITY);

    int e = 0;
    for (; e + 8 <= cnt; e += 8) {
        ushort4 ja = *(const ushort4*)&lists[w][e];
        ushort4 jb = *(const ushort4*)&lists[w][e + 4];
        float4 v0 = *(const float4*)(base + (int)ja.x * ZZ);
        float4 v1 = *(const float4*)(base + (int)ja.y * ZZ);
        float4 v2 = *(const float4*)(base + (int)ja.z * ZZ);
        float4 v3 = *(const float4*)(base + (int)ja.w * ZZ);
        float4 v4 = *(const float4*)(base + (int)jb.x * ZZ);
        float4 v5 = *(const float4*)(base + (int)jb.y * ZZ);
        float4 v6 = *(const float4*)(base + (int)jb.z * ZZ);
        float4 v7 = *(const float4*)(base + (int)jb.w * ZZ);
        acc.x = fmaxf(acc.x, fmaxf(fmaxf(fmaxf(v0.x,v1.x),fmaxf(v2.x,v3.x)),
                                   fmaxf(fmaxf(v4.x,v5.x),fmaxf(v6.x,v7.x))));
        acc.y = fmaxf(acc.y, fmaxf(fmaxf(fmaxf(v0.y,v1.y),fmaxf(v2.y,v3.y)),
                                   fmaxf(fmaxf(v4.y,v5.y),fmaxf(v6.y,v7.y))));
        acc.z = fmaxf(acc.z, fmaxf(fmaxf(fmaxf(v0.z,v1.z),fmaxf(v2.z,v3.z)),
                                   fmaxf(fmaxf(v4.z,v5.z),fmaxf(v6.z,v7.z))));
        acc.w = fmaxf(acc.w, fmaxf(fmaxf(fmaxf(v0.w,v1.w),fmaxf(v2.w,v3.w)),
                                   fmaxf(fmaxf(v4.w,v5.w),fmaxf(v6.w,v7.w))));
    }
    for (; e + 4 <= cnt; e += 4) {
        ushort4 jj = *(const ushort4*)&lists[w][e];
        float4 v0 = *(const float4*)(base + (int)jj.x * ZZ);
        float4 v1 = *(const float4*)(base + (int)jj.y * ZZ);
        float4 v2 = *(const float4*)(base + (int)jj.z * ZZ);
        float4 v3 = *(const float4*)(base + (int)jj.w * ZZ);
        acc.x = fmaxf(fmaxf(fmaxf(acc.x, v0.x), fmaxf(v1.x, v2.x)), v3.x);
        acc.y = fmaxf(fmaxf(fmaxf(acc.y, v0.y), fmaxf(v1.y, v2.y)), v3.y);
        acc.z = fmaxf(fmaxf(fmaxf(acc.z, v0.z), fmaxf(v1.z, v2.z)), v3.z);
        acc.w = fmaxf(fmaxf(fmaxf(acc.w, v0.w), fmaxf(v1.w, v2.w)), v3.w);
    }
    for (; e < cnt; e++) {
        int j = lists[w][e];
        float4 v = *(const float4*)(base + j * ZZ);
        acc.x = fmaxf(acc.x, v.x);
        acc.y = fmaxf(acc.y, v.y);
        acc.z = fmaxf(acc.z, v.z);
        acc.w = fmaxf(acc.w, v.w);
    }

    const size_t off = ((size_t)b * KK + i0 + w) * ZZ + lane * 4;
    float4 m1 = *(const float4*)(g_m1 + off);
    float4 m;
    m.x = fmaxf(m1.x + acc.x, 0.f);
    m.y = fmaxf(m1.y + acc.y, 0.f);
    m.z = fmaxf(m1.z + acc.z, 0.f);
    m.w = fmaxf(m1.w + acc.w, 0.f);
    *(float4*)(g_m + off) = m;
}

// ---------------------------------------------------------------------------
// K3 core: split-K GEMM partials.
// ksplit 0: p0 = z @ WuL^T ; ksplit 1: p1 = m @ WuR^T.
// grid (128 rowtiles, 2 colhalves, 2 ksplit), 128 threads.
// CTA: 32 rows x 64 cols, micro 4x4 — identical shape to k1.
// ---------------------------------------------------------------------------
__global__ __launch_bounds__(128, 4) void k3_gemm(
    const float* __restrict__ z,
    const float* __restrict__ Wu)
{
    __shared__ __align__(16) float Xs[32][68];
    __shared__ __align__(16) float Ws[64][76];

    const int tid    = threadIdx.x;
    const int row0   = blockIdx.x * 32;
    const int N0     = blockIdx.y * 64;
    const int ksplit = blockIdx.z;
    const float* __restrict__ src =
        ksplit ? (g_m + (size_t)row0 * ZZ) : (z + (size_t)row0 * ZZ);
    const int koff = ksplit * ZZ;

    const int rg = tid >> 4;
    const int ng = tid & 15;

    u64 acc[4][4];
    #pragma unroll
    for (int r = 0; r < 4; r++)
        #pragma unroll
        for (int c = 0; c < 4; c++) acc[r][c] = 0ull;

    for (int kc = 0; kc < ZZ; kc += 64) {
        #pragma unroll
        for (int it = 0; it < 4; it++) {           // X: 32 rows x 64 k
            int f = tid + it * 128;
            int r = f >> 4, kq = f & 15;
            *(float4*)&Xs[r][4*kq] = *(const float4*)(src + r * ZZ + kc + 4*kq);
        }
        #pragma unroll
        for (int it = 0; it < 8; it++) {           // W: 64 n x 64 k
            int f = tid + it * 128;
            int n = f >> 4, kq = f & 15;
            *(float4*)&Ws[n][4*kq] =
                *(const float4*)&Wu[(N0 + n) * (2 * ZZ) + koff + kc + 4*kq];
        }
        __syncthreads();

        #pragma unroll
        for (int kq = 0; kq < 16; kq++) {
            ulonglong2 xq[4];
            #pragma unroll
            for (int rr = 0; rr < 4; rr++)
                xq[rr] = *(const ulonglong2*)&Xs[4*rg + rr][4*kq];
            #pragma unroll
            for (int cc = 0; cc < 4; cc++) {
                ulonglong2 wq = *(const ulonglong2*)&Ws[ng + 16*cc][4*kq];
                #pragma unroll
                for (int rr = 0; rr < 4; rr++) {
                    fma2(acc[rr][cc], xq[rr].x, wq.x);
                    fma2(acc[rr][cc], xq[rr].y, wq.y);
                }
            }
        }
        __syncthreads();
    }

    float* dst = g_p + (size_t)ksplit * (BB * KK * HH);
    #pragma unroll
    for (int cc = 0; cc < 4; cc++) {
        int col = N0 + ng + 16*cc;
        #pragma unroll
        for (int rr = 0; rr < 4; rr++) {
            float lo, hi; unpack2(acc[rr][cc], lo, hi);
            dst[(row0 + 4*rg + rr) * HH + col] = lo + hi;
        }
    }
}

// ---------------------------------------------------------------------------
// K3 epilogue: out = relu(p0 + p1 + bu), float4-vectorized.
// ---------------------------------------------------------------------------
__global__ __launch_bounds__(256) void k3_epi(
    const float* __restrict__ bu, float* __restrict__ out)
{
    int t = blockIdx.x * 256 + threadIdx.x;      // 0..131071 (float4 lanes)
    const float4* p4 = (const float4*)g_p;
    float4 a = p4[t];
    float4 c = p4[(BB * KK * HH / 4) + t];
    float4 bb = __ldg(&((const float4*)bu)[t & 31]);
    float4 o;
    o.x = fmaxf(a.x + c.x + bb.x, 0.f);
    o.y = fmaxf(a.y + c.y + bb.y, 0.f);
    o.z = fmaxf(a.z + c.z + bb.z, 0.f);
    o.w = fmaxf(a.w + c.w + bb.w, 0.f);
    ((float4*)out)[t] = o;
}

// ---------------------------------------------------------------------------
extern "C" void kernel_launch(void* const* d_in, const int* in_sizes, int n_in,
                              void* d_out, int out_size)
{
    const float* z  = (const float*)d_in[0];
    const int*   P  = (const int*)  d_in[1];
    const float* W1 = (const float*)d_in[2];
    const float* b1 = (const float*)d_in[3];
    const float* W2 = (const float*)d_in[4];
    const float* b2 = (const float*)d_in[5];
    const float* Wu = (const float*)d_in[6];
    const float* bu = (const float*)d_in[7];
    float* out = (float*)d_out;

    k1_gemm<<<dim3(BB * KK / 32, 4), 128>>>(z, W1, b1, W2, b2);
    k2a_pairmax<<<256, 256>>>();
    k2_maxmsg<<<dim3(KK / 16, BB), 512>>>(P);
    k3_gemm<<<dim3(BB * KK / 32, 2, 2), 128>>>(z, Wu);
    k3_epi<<<BB * KK * HH / 4 / 256, 256>>>(bu, out);
}